// round 15
// baseline (speedup 1.0000x reference)
#include <cuda_runtime.h>
#include <cuda_bf16.h>
#include <math.h>

#define Nn   131072
#define Ee   1048576
#define ETOT (Ee + Nn)
#define INC  256
#define Hh   128
#define OUTC 64
#define Gg   128
#define NPG  1024
#define NB   256
#define SEG  (Nn / NB)
#define MAXD 64
#define TILEW 4608
#define GSMEM  (4 * TILEW * 4)                      // gemm1: 73728 B
#define AST   132                                   // A-tile word stride
#define AGS   (128 * AST * 4 + 2 * TILEW * 4 + 4096) // fused: 108544 B

// ---------------- scratch (double-buffered layer outputs) ----------------
__device__ __align__(16) __nv_bfloat16 g_linhA[(size_t)Nn * Hh];
__device__ __align__(16) __nv_bfloat16 g_linhB[(size_t)Nn * Hh];
__device__ float g_esA[Nn];
__device__ float g_esB[Nn];
__device__ float g_edA[Nn];
__device__ float g_edB[Nn];
__device__ __align__(16) int g_cnt[Nn];
__device__ int   g_off[Nn + 1];
__device__ int   g_cur[Nn];
__device__ int   g_csr[ETOT];
__device__ int   g_bsum[NB];
__device__ __align__(16) float g_pool[Gg * Hh];
__device__ __align__(16) float g_news[Gg * Hh];
__device__ float g_eh1[Gg * OUTC];
__device__ float g_ee1[Gg * OUTC];
__device__ float g_eh2[Gg * OUTC];
__device__ float g_ee2[Gg * OUTC];

__device__ __forceinline__ float atomicMaxF(float* a, float v) {
    if (v >= 0.f) return __int_as_float(atomicMax((int*)a, __float_as_int(v)));
    return __uint_as_float(atomicMin((unsigned int*)a, __float_as_uint(v)));
}

__device__ __forceinline__ void mma_tf32(float* d, const unsigned* a, const unsigned* b) {
    asm volatile(
        "mma.sync.aligned.m16n8k8.row.col.f32.tf32.tf32.f32 "
        "{%0,%1,%2,%3}, {%4,%5,%6,%7}, {%8,%9}, {%0,%1,%2,%3};"
        : "+f"(d[0]), "+f"(d[1]), "+f"(d[2]), "+f"(d[3])
        : "r"(a[0]), "r"(a[1]), "r"(a[2]), "r"(a[3]), "r"(b[0]), "r"(b[1]));
}

__device__ __forceinline__ void cpa16(unsigned dst, const float* src) {
    asm volatile("cp.async.ca.shared.global [%0], [%1], 16;" :: "r"(dst), "l"(src));
}
__device__ __forceinline__ void cpa_commit() { asm volatile("cp.async.commit_group;"); }
__device__ __forceinline__ void cpa_wait()   { asm volatile("cp.async.wait_group 0;"); }

// ---------------- CSR build ----------------
__global__ void k_zero_cnt() {
    int stride = gridDim.x * blockDim.x;
    for (int i = blockIdx.x * blockDim.x + threadIdx.x; i < Nn; i += stride) g_cnt[i] = 1;
}

__global__ void k_count(const int* __restrict__ ei) {
    int stride = gridDim.x * blockDim.x;
    const int4* d4 = (const int4*)(ei + Ee);
    for (int i = blockIdx.x * blockDim.x + threadIdx.x; i < Ee / 4; i += stride) {
        int4 d = d4[i];
        atomicAdd(&g_cnt[d.x], 1);
        atomicAdd(&g_cnt[d.y], 1);
        atomicAdd(&g_cnt[d.z], 1);
        atomicAdd(&g_cnt[d.w], 1);
    }
}

__global__ __launch_bounds__(256) void k_scan1() {
    __shared__ int sm[256];
    int b = blockIdx.x, t = threadIdx.x;
    int2 c = *(const int2*)&g_cnt[b * SEG + t * 2];
    sm[t] = c.x + c.y;
    __syncthreads();
#pragma unroll
    for (int o = 128; o; o >>= 1) {
        if (t < o) sm[t] += sm[t + o];
        __syncthreads();
    }
    if (t == 0) g_bsum[b] = sm[0];
}

__global__ __launch_bounds__(256) void k_scan2() {
    __shared__ int sm[NB];
    int t = threadIdx.x;
    int v = g_bsum[t];
    sm[t] = v;
    __syncthreads();
    for (int o = 1; o < NB; o <<= 1) {
        int u = (t >= o) ? sm[t - o] : 0;
        __syncthreads();
        sm[t] += u;
        __syncthreads();
    }
    g_bsum[t] = sm[t] - v;
}

__global__ __launch_bounds__(256) void k_scan3() {
    __shared__ int sm[256];
    int b = blockIdx.x, t = threadIdx.x;
    int i0 = b * SEG + t * 2;
    int2 c = *(const int2*)&g_cnt[i0];
    int s = c.x + c.y;
    sm[t] = s;
    __syncthreads();
    for (int o = 1; o < 256; o <<= 1) {
        int u = (t >= o) ? sm[t - o] : 0;
        __syncthreads();
        sm[t] += u;
        __syncthreads();
    }
    int run = g_bsum[b] + sm[t] - s;
    g_off[i0] = run;
    g_off[i0 + 1] = run + c.x;
    g_csr[run] = i0;
    g_csr[run + c.x] = i0 + 1;
    g_cur[i0] = run + 1;
    g_cur[i0 + 1] = run + c.x + 1;
    if (b == NB - 1 && t == 255) g_off[Nn] = ETOT;
}

__global__ void k_fill(const int* __restrict__ ei) {
    int stride = gridDim.x * blockDim.x;
    const int4* s4 = (const int4*)ei;
    const int4* d4 = (const int4*)(ei + Ee);
    for (int i = blockIdx.x * blockDim.x + threadIdx.x; i < Ee / 4; i += stride) {
        int4 s = s4[i];
        int4 d = d4[i];
        g_csr[atomicAdd(&g_cur[d.x], 1)] = s.x;
        g_csr[atomicAdd(&g_cur[d.y], 1)] = s.y;
        g_csr[atomicAdd(&g_cur[d.z], 1)] = s.z;
        g_csr[atomicAdd(&g_cur[d.w], 1)] = s.w;
    }
}

// ---------------- tf32 GEMM for layer 1 (x fp32 input -> buf A) ----------------
__global__ __launch_bounds__(256, 2) void k_gemm_tc(const float* __restrict__ A, int K,
                                                    const float* __restrict__ W,
                                                    const float* __restrict__ av,
                                                    const float* __restrict__ dv) {
    extern __shared__ unsigned smu[];
    unsigned* AsB[2] = { smu, smu + TILEW };
    unsigned* BsB[2] = { smu + 2 * TILEW, smu + 3 * TILEW };

    int tid = threadIdx.x;
    int lane = tid & 31;
    int wid = tid >> 5;
    int warp_m = wid & 3;
    int warp_n = wid >> 2;
    int gID = lane >> 2;
    int tID = lane & 3;
    int rowBase = blockIdx.x * 128;
    int NCH = K >> 5;

    auto loadA = [&](int buf, int k0) {
#pragma unroll
        for (int l = 0; l < 4; l++) {
            int slot = tid + 256 * l;
            int r = slot >> 3;
            int c4 = (slot & 7) << 2;
            unsigned dst = (unsigned)__cvta_generic_to_shared(&AsB[buf][r * 36 + c4]);
            cpa16(dst, A + (size_t)(rowBase + r) * K + k0 + c4);
        }
        cpa_commit();
    };
    auto ldgW = [&](int k0, float* wreg) {
#pragma unroll
        for (int it = 0; it < 16; it++) {
            int c = wid + it * 8;
            int kl = (c & 7) * 4 + tID;
            int n = (c >> 3) * 8 + gID;
            wreg[it] = W[(size_t)(k0 + kl) * 128 + n];
        }
    };
    auto stsW = [&](int buf, const float* wreg) {
#pragma unroll
        for (int it = 0; it < 16; it++) {
            int c = wid + it * 8;
            int kl = (c & 7) * 4 + tID;
            int n = (c >> 3) * 8 + gID;
            BsB[buf][n * 36 + kl] = __float_as_uint(wreg[it]);
        }
    };

    float acc[2][8][4];
#pragma unroll
    for (int mi = 0; mi < 2; mi++)
#pragma unroll
        for (int ni = 0; ni < 8; ni++)
#pragma unroll
            for (int j = 0; j < 4; j++) acc[mi][ni][j] = 0.f;

    loadA(0, 0);
    {
        float w0[16];
        ldgW(0, w0);
        stsW(0, w0);
    }

    for (int ch = 0; ch < NCH; ch++) {
        int buf = ch & 1;
        bool more = (ch + 1 < NCH);
        float wreg[16];
        if (more) ldgW((ch + 1) << 5, wreg);
        cpa_wait();
        __syncthreads();
        if (more) loadA(buf ^ 1, (ch + 1) << 5);

        unsigned* As = AsB[buf];
        unsigned* Bs = BsB[buf];
#pragma unroll
        for (int kc = 0; kc < 4; kc++) {
            int kk = kc * 8;
            unsigned af[2][4];
#pragma unroll
            for (int mi = 0; mi < 2; mi++) {
                int r = warp_m * 32 + mi * 16 + gID;
                af[mi][0] = As[r * 36 + kk + tID];
                af[mi][1] = As[(r + 8) * 36 + kk + tID];
                af[mi][2] = As[r * 36 + kk + tID + 4];
                af[mi][3] = As[(r + 8) * 36 + kk + tID + 4];
            }
#pragma unroll
            for (int ni = 0; ni < 8; ni++) {
                int n = warp_n * 64 + ni * 8 + gID;
                unsigned bf[2];
                bf[0] = Bs[n * 36 + kk + tID];
                bf[1] = Bs[n * 36 + kk + tID + 4];
                mma_tf32(acc[0][ni], af[0], bf);
                mma_tf32(acc[1][ni], af[1], bf);
            }
        }
        if (more) stsW(buf ^ 1, wreg);
    }

    float pes[2][2] = {{0.f, 0.f}, {0.f, 0.f}};
    float ped[2][2] = {{0.f, 0.f}, {0.f, 0.f}};
#pragma unroll
    for (int mi = 0; mi < 2; mi++) {
        int r0 = rowBase + warp_m * 32 + mi * 16 + gID;
        int r1 = r0 + 8;
#pragma unroll
        for (int ni = 0; ni < 8; ni++) {
            int c0 = warp_n * 64 + ni * 8 + 2 * tID;
            float a0v = __ldg(av + c0), a1v = __ldg(av + c0 + 1);
            float d0v = __ldg(dv + c0), d1v = __ldg(dv + c0 + 1);
            float* d = acc[mi][ni];
            __nv_bfloat162 p0, p1;
            p0.x = __float2bfloat16(d[0]); p0.y = __float2bfloat16(d[1]);
            p1.x = __float2bfloat16(d[2]); p1.y = __float2bfloat16(d[3]);
            *(__nv_bfloat162*)(g_linhA + (size_t)r0 * Hh + c0) = p0;
            *(__nv_bfloat162*)(g_linhA + (size_t)r1 * Hh + c0) = p1;
            pes[mi][0] += d[0] * a0v + d[1] * a1v;
            pes[mi][1] += d[2] * a0v + d[3] * a1v;
            ped[mi][0] += d[0] * d0v + d[1] * d1v;
            ped[mi][1] += d[2] * d0v + d[3] * d1v;
        }
    }
    __syncthreads();
    float* esp = (float*)smu;
#pragma unroll
    for (int mi = 0; mi < 2; mi++)
#pragma unroll
        for (int h = 0; h < 2; h++) {
            float v1 = pes[mi][h], v2 = ped[mi][h];
            v1 += __shfl_xor_sync(0xffffffffu, v1, 1);
            v1 += __shfl_xor_sync(0xffffffffu, v1, 2);
            v2 += __shfl_xor_sync(0xffffffffu, v2, 1);
            v2 += __shfl_xor_sync(0xffffffffu, v2, 2);
            if (tID == 0) {
                int rl = warp_m * 32 + mi * 16 + h * 8 + gID;
                esp[warp_n * 128 + rl] = v1;
                esp[256 + warp_n * 128 + rl] = v2;
            }
        }
    __syncthreads();
    if (tid < 128) {
        g_esA[rowBase + tid] = esp[tid] + esp[128 + tid];
        g_edA[rowBase + tid] = esp[256 + tid] + esp[384 + tid];
    }
}

// ---------------- fused agg(layer l) + gemm(layer l+1) ----------------
// Block owns 128 nodes: phase 1 aggregates into smem A tile (fp32),
// phase 2 runs the MMA GEMM from smem. Reads buf ib, writes buf ib^1.
__device__ __forceinline__ void gat_fma(float4& acc, float ex, const uint2& raw) {
    float2 f01 = __bfloat1622float2(*(const __nv_bfloat162*)&raw.x);
    float2 f23 = __bfloat1622float2(*(const __nv_bfloat162*)&raw.y);
    acc.x += ex * f01.x;
    acc.y += ex * f01.y;
    acc.z += ex * f23.x;
    acc.w += ex * f23.y;
}

__global__ __launch_bounds__(256, 2) void k_ag(const float* __restrict__ bias, int ib,
                                               const float* __restrict__ W,
                                               const float* __restrict__ av,
                                               const float* __restrict__ dv) {
    extern __shared__ unsigned smu[];
    float*    Af  = (float*)smu;                        // [128][AST]
    unsigned* BsB[2] = { smu + 128 * AST, smu + 128 * AST + TILEW };
    float*    s_t = (float*)(smu + 128 * AST + 2 * TILEW);   // [8][64]
    int*      s_s = (int*)(s_t + 8 * MAXD);                  // [8][64]

    const __nv_bfloat16* lin = ib ? g_linhB : g_linhA;
    const float* esIn = ib ? g_esB : g_esA;
    const float* edIn = ib ? g_edB : g_edA;
    __nv_bfloat16* linO = ib ? g_linhA : g_linhB;
    float* esO = ib ? g_esA : g_esB;
    float* edO = ib ? g_edA : g_edB;

    int tid = threadIdx.x;
    int lane = tid & 31;
    int wid = tid >> 5;
    int rowBase = blockIdx.x * 128;

    // W chunk-0 LDGs in flight across phase 1
    int warp_m = wid & 3;
    int warp_n = wid >> 2;
    int gID = lane >> 2;
    int tID = lane & 3;
    auto ldgW = [&](int k0, float* wreg) {
#pragma unroll
        for (int it = 0; it < 16; it++) {
            int c = wid + it * 8;
            int kl = (c & 7) * 4 + tID;
            int n = (c >> 3) * 8 + gID;
            wreg[it] = W[(size_t)(k0 + kl) * 128 + n];
        }
    };
    auto stsW = [&](int buf, const float* wreg) {
#pragma unroll
        for (int it = 0; it < 16; it++) {
            int c = wid + it * 8;
            int kl = (c & 7) * 4 + tID;
            int n = (c >> 3) * 8 + gID;
            BsB[buf][n * 36 + kl] = __float_as_uint(wreg[it]);
        }
    };
    float w0[16];
    ldgW(0, w0);

    // ---- phase 1: aggregate 16 nodes per warp into Af ----
    float* st = s_t + wid * MAXD;
    int*   ss = s_s + wid * MAXD;
    for (int it = 0; it < 16; it++) {
        int d = rowBase + wid * 16 + it;
        int beg = g_off[d], end = g_off[d + 1];
        int deg = end - beg;
        float edv = edIn[d];

        float den = 0.f;
        for (int k = lane; k < deg; k += 32) {
            int s = g_csr[beg + k];
            float t = esIn[s] + edv;
            t = (t >= 0.f) ? t : 0.2f * t;
            float ex = __expf(t);
            den += ex;
            if (k < MAXD) { st[k] = ex; ss[k] = s; }
        }
#pragma unroll
        for (int o = 16; o; o >>= 1) den += __shfl_xor_sync(0xffffffffu, den, o);
        __syncwarp();

        float4 acc = make_float4(0.f, 0.f, 0.f, 0.f);
        float4 acc2 = make_float4(0.f, 0.f, 0.f, 0.f);
        int kc = (deg < MAXD) ? deg : MAXD;
        int k = 0;
        for (; k + 4 <= kc; k += 4) {
            float e0 = st[k + 0], e1 = st[k + 1], e2 = st[k + 2], e3 = st[k + 3];
            int r0 = ss[k + 0], r1 = ss[k + 1], r2 = ss[k + 2], r3 = ss[k + 3];
            uint2 q0 = *((const uint2*)(lin + (size_t)r0 * Hh) + lane);
            uint2 q1 = *((const uint2*)(lin + (size_t)r1 * Hh) + lane);
            uint2 q2 = *((const uint2*)(lin + (size_t)r2 * Hh) + lane);
            uint2 q3 = *((const uint2*)(lin + (size_t)r3 * Hh) + lane);
            gat_fma(acc, e0, q0);
            gat_fma(acc2, e1, q1);
            gat_fma(acc, e2, q2);
            gat_fma(acc2, e3, q3);
        }
        for (; k < kc; k++) {
            float ex = st[k];
            int   sk = ss[k];
            uint2 q0 = *((const uint2*)(lin + (size_t)sk * Hh) + lane);
            gat_fma(acc, ex, q0);
        }
        for (k = MAXD; k < deg; k++) {
            int sk = g_csr[beg + k];
            float t = esIn[sk] + edv;
            t = (t >= 0.f) ? t : 0.2f * t;
            float ex = __expf(t);
            uint2 q0 = *((const uint2*)(lin + (size_t)sk * Hh) + lane);
            gat_fma(acc, ex, q0);
        }
        acc.x += acc2.x;
        acc.y += acc2.y;
        acc.z += acc2.z;
        acc.w += acc2.w;

        float inv = 1.f / (den + 1e-16f);
        float4 bv = *((const float4*)bias + lane);
        float* dst = Af + (size_t)(wid * 16 + it) * AST + lane * 4;
        dst[0] = fmaxf(acc.x * inv + bv.x, 0.f);
        dst[1] = fmaxf(acc.y * inv + bv.y, 0.f);
        dst[2] = fmaxf(acc.z * inv + bv.z, 0.f);
        dst[3] = fmaxf(acc.w * inv + bv.w, 0.f);
    }
    __syncthreads();   // Af complete
    stsW(0, w0);

    // ---- phase 2: GEMM from smem A tile (K = 128, 4 chunks) ----
    const unsigned* Au = (const unsigned*)Af;
    float acc[2][8][4];
#pragma unroll
    for (int mi = 0; mi < 2; mi++)
#pragma unroll
        for (int ni = 0; ni < 8; ni++)
#pragma unroll
            for (int j = 0; j < 4; j++) acc[mi][ni][j] = 0.f;

    for (int ch = 0; ch < 4; ch++) {
        int buf = ch & 1;
        bool more = (ch + 1 < 4);
        float wreg[16];
        if (more) ldgW((ch + 1) << 5, wreg);
        __syncthreads();   // Bs[buf] stores visible; prior compute done everywhere

        unsigned* Bs = BsB[buf];
        int k0 = ch << 5;
#pragma unroll
        for (int kc = 0; kc < 4; kc++) {
            int kk = kc * 8;
            unsigned af[2][4];
#pragma unroll
            for (int mi = 0; mi < 2; mi++) {
                int r = warp_m * 32 + mi * 16 + gID;
                af[mi][0] = Au[r * AST + k0 + kk + tID];
                af[mi][1] = Au[(r + 8) * AST + k0 + kk + tID];
                af[mi][2] = Au[r * AST + k0 + kk + tID + 4];
                af[mi][3] = Au[(r + 8) * AST + k0 + kk + tID + 4];
            }
#pragma unroll
            for (int ni = 0; ni < 8; ni++) {
                int n = warp_n * 64 + ni * 8 + gID;
                unsigned bf[2];
                bf[0] = Bs[n * 36 + kk + tID];
                bf[1] = Bs[n * 36 + kk + tID + 4];
                mma_tf32(acc[0][ni], af[0], bf);
                mma_tf32(acc[1][ni], af[1], bf);
            }
        }
        if (more) stsW(buf ^ 1, wreg);
    }

    // ---- epilogue (writes out-buffer) ----
    float pes[2][2] = {{0.f, 0.f}, {0.f, 0.f}};
    float ped[2][2] = {{0.f, 0.f}, {0.f, 0.f}};
#pragma unroll
    for (int mi = 0; mi < 2; mi++) {
        int r0 = rowBase + warp_m * 32 + mi * 16 + gID;
        int r1 = r0 + 8;
#pragma unroll
        for (int ni = 0; ni < 8; ni++) {
            int c0 = warp_n * 64 + ni * 8 + 2 * tID;
            float a0v = __ldg(av + c0), a1v = __ldg(av + c0 + 1);
            float d0v = __ldg(dv + c0), d1v = __ldg(dv + c0 + 1);
            float* d = acc[mi][ni];
            __nv_bfloat162 p0, p1;
            p0.x = __float2bfloat16(d[0]); p0.y = __float2bfloat16(d[1]);
            p1.x = __float2bfloat16(d[2]); p1.y = __float2bfloat16(d[3]);
            *(__nv_bfloat162*)(linO + (size_t)r0 * Hh + c0) = p0;
            *(__nv_bfloat162*)(linO + (size_t)r1 * Hh + c0) = p1;
            pes[mi][0] += d[0] * a0v + d[1] * a1v;
            pes[mi][1] += d[2] * a0v + d[3] * a1v;
            ped[mi][0] += d[0] * d0v + d[1] * d1v;
            ped[mi][1] += d[2] * d0v + d[3] * d1v;
        }
    }
    __syncthreads();
    float* esp = s_t;   // 512 floats: s_t area (2048 B) exactly
#pragma unroll
    for (int mi = 0; mi < 2; mi++)
#pragma unroll
        for (int h = 0; h < 2; h++) {
            float v1 = pes[mi][h], v2 = ped[mi][h];
            v1 += __shfl_xor_sync(0xffffffffu, v1, 1);
            v1 += __shfl_xor_sync(0xffffffffu, v1, 2);
            v2 += __shfl_xor_sync(0xffffffffu, v2, 1);
            v2 += __shfl_xor_sync(0xffffffffu, v2, 2);
            if (tID == 0) {
                int rl = warp_m * 32 + mi * 16 + h * 8 + gID;
                esp[warp_n * 128 + rl] = v1;
                ((float*)s_s)[warp_n * 128 + rl] = v2;   // s_s area for ed parts
            }
        }
    __syncthreads();
    if (tid < 128) {
        esO[rowBase + tid] = esp[tid] + esp[128 + tid];
        edO[rowBase + tid] = ((float*)s_s)[tid] + ((float*)s_s)[128 + tid];
    }
}

// ---------------- final agg (layer 3) + global max pool ----------------
__global__ __launch_bounds__(256, 8) void k_agg3(const float* __restrict__ bias) {
    __shared__ float s_t[8][MAXD];
    __shared__ int   s_s[8][MAXD];
    __shared__ float s_pm[128];
    int wip = (threadIdx.x >> 5) & 7;
    int lane = threadIdx.x & 31;
    int d = blockIdx.x * 8 + wip;
    int beg = g_off[d], end = g_off[d + 1];
    int deg = end - beg;
    float edv = g_edA[d];

    float den = 0.f;
    for (int k = lane; k < deg; k += 32) {
        int s = g_csr[beg + k];
        float t = g_esA[s] + edv;
        t = (t >= 0.f) ? t : 0.2f * t;
        float ex = __expf(t);
        den += ex;
        if (k < MAXD) { s_t[wip][k] = ex; s_s[wip][k] = s; }
    }
#pragma unroll
    for (int o = 16; o; o >>= 1) den += __shfl_xor_sync(0xffffffffu, den, o);
    __syncwarp();

    float4 acc = make_float4(0.f, 0.f, 0.f, 0.f);
    float4 acc2 = make_float4(0.f, 0.f, 0.f, 0.f);
    int kc = (deg < MAXD) ? deg : MAXD;
    int k = 0;
    for (; k + 4 <= kc; k += 4) {
        float e0 = s_t[wip][k + 0], e1 = s_t[wip][k + 1];
        float e2 = s_t[wip][k + 2], e3 = s_t[wip][k + 3];
        int r0 = s_s[wip][k + 0], r1 = s_s[wip][k + 1];
        int r2 = s_s[wip][k + 2], r3 = s_s[wip][k + 3];
        uint2 q0 = *((const uint2*)(g_linhA + (size_t)r0 * Hh) + lane);
        uint2 q1 = *((const uint2*)(g_linhA + (size_t)r1 * Hh) + lane);
        uint2 q2 = *((const uint2*)(g_linhA + (size_t)r2 * Hh) + lane);
        uint2 q3 = *((const uint2*)(g_linhA + (size_t)r3 * Hh) + lane);
        gat_fma(acc, e0, q0);
        gat_fma(acc2, e1, q1);
        gat_fma(acc, e2, q2);
        gat_fma(acc2, e3, q3);
    }
    for (; k < kc; k++) {
        float ex = s_t[wip][k];
        int   sk = s_s[wip][k];
        uint2 q0 = *((const uint2*)(g_linhA + (size_t)sk * Hh) + lane);
        gat_fma(acc, ex, q0);
    }
    for (k = MAXD; k < deg; k++) {
        int sk = g_csr[beg + k];
        float t = g_esA[sk] + edv;
        t = (t >= 0.f) ? t : 0.2f * t;
        float ex = __expf(t);
        uint2 q0 = *((const uint2*)(g_linhA + (size_t)sk * Hh) + lane);
        gat_fma(acc, ex, q0);
    }
    acc.x += acc2.x;
    acc.y += acc2.y;
    acc.z += acc2.z;
    acc.w += acc2.w;

    float inv = 1.f / (den + 1e-16f);
    float4 bv = *((const float4*)bias + lane);
    float4 r;
    r.x = fmaxf(acc.x * inv + bv.x, 0.f);
    r.y = fmaxf(acc.y * inv + bv.y, 0.f);
    r.z = fmaxf(acc.z * inv + bv.z, 0.f);
    r.w = fmaxf(acc.w * inv + bv.w, 0.f);

    if (threadIdx.x < 128) s_pm[threadIdx.x] = 0.f;
    __syncthreads();
    atomicMaxF(&s_pm[lane * 4 + 0], r.x);
    atomicMaxF(&s_pm[lane * 4 + 1], r.y);
    atomicMaxF(&s_pm[lane * 4 + 2], r.z);
    atomicMaxF(&s_pm[lane * 4 + 3], r.w);
    __syncthreads();
    if (threadIdx.x < 128) {
        int g = (blockIdx.x * 8) >> 10;
        atomicMaxF(&g_pool[g * Hh + threadIdx.x], s_pm[threadIdx.x]);
    }
}

// ---------------- pool init ----------------
__global__ void k_pool_init() {
    int i = blockIdx.x * blockDim.x + threadIdx.x;
    if (i < Gg * Hh) g_pool[i] = 0.f;
}

// ---------------- news projection ----------------
__global__ void k_news(const float* __restrict__ x,
                       const float* __restrict__ Wn, const float* __restrict__ bn) {
    __shared__ float arow[INC];
    int i = blockIdx.x, j = threadIdx.x;
    for (int k = j; k < INC; k += Hh) arow[k] = x[(long long)i * NPG * INC + k];
    __syncthreads();
    float s = bn[j];
    for (int k = 0; k < INC; k++) s += arow[k] * Wn[k * Hh + j];
    g_news[i * Hh + j] = fmaxf(s, 0.f);
}

// ---------------- merged head ----------------
__global__ void k_head(const float* __restrict__ W0, const float* __restrict__ b0,
                       const float* __restrict__ Wa1, const float* __restrict__ ba1,
                       const float* __restrict__ Wa2, const float* __restrict__ ba2) {
    __shared__ float hg[Hh], nw[Hh], pr[Hh];
    int i = blockIdx.x, j = threadIdx.x;
    pr[j] = g_pool[i * Hh + j];
    nw[j] = g_news[i * Hh + j];
    __syncthreads();
    float s = b0[j];
    for (int k = 0; k < Hh; k++) s += pr[k] * W0[k * Hh + j];
    hg[j] = fmaxf(s, 0.f);
    __syncthreads();
#pragma unroll
    for (int q = 0; q < 2; q++) {
        int o = j + q * 128;
        int y = o >> 6, c = o & 63;
        const float* Arow = (y == 0 || y == 3) ? hg : nw;
        const float* W = (y == 0) ? Wa1 : (y == 1) ? (Wa1 + Hh * OUTC)
                       : (y == 2) ? Wa2 : (Wa2 + Hh * OUTC);
        float acc = (y == 0) ? ba1[c] : (y == 2) ? ba2[c] : 0.f;
        for (int k = 0; k < Hh; k++) acc += Arow[k] * W[k * OUTC + c];
        float* C = (y == 0) ? g_eh1 : (y == 1) ? g_ee1 : (y == 2) ? g_eh2 : g_ee2;
        C[i * OUTC + c] = acc;
    }
}

// ---------------- merged Bahdanau + final ----------------
__global__ void k_bahfin(const float* __restrict__ v1, const float* __restrict__ v2,
                         const float* __restrict__ Wl, const float* __restrict__ bl,
                         float* __restrict__ out) {
    __shared__ float se1[OUTC], se2[OUTC], sv1[OUTC], sv2[OUTC];
    __shared__ float fused[2 * Hh];
    int i = blockIdx.x, j = threadIdx.x;
    if (j < OUTC) { se1[j] = g_eh1[i * OUTC + j]; sv1[j] = v1[j]; }
    else          { int c = j - OUTC; se2[c] = g_eh2[i * OUTC + c]; sv2[c] = v2[c]; }
    __syncthreads();
    float a = 0.f, b = 0.f;
#pragma unroll 8
    for (int k = 0; k < OUTC; k++) a += tanhf(se1[k] + g_ee1[j * OUTC + k]) * sv1[k];
#pragma unroll 8
    for (int k = 0; k < OUTC; k++) b += tanhf(se2[k] + g_ee2[j * OUTC + k]) * sv2[k];
    fused[j] = a;
    fused[Hh + j] = b;
    __syncthreads();
    if (j < OUTC) {
        float s = bl[j];
        for (int k = 0; k < 2 * Hh; k++) s += fused[k] * Wl[k * OUTC + j];
        out[i * OUTC + j] = 1.f / (1.f + __expf(-s));
    }
}

// ---------------- launch ----------------
extern "C" void kernel_launch(void* const* d_in, const int* in_sizes, int n_in,
                              void* d_out, int out_size) {
    const float* x   = (const float*)d_in[0];
    const int*   ei  = (const int*)d_in[1];
    const float* W1  = (const float*)d_in[3];
    const float* as1 = (const float*)d_in[4];
    const float* ad1 = (const float*)d_in[5];
    const float* b1  = (const float*)d_in[6];
    const float* W2  = (const float*)d_in[7];
    const float* as2 = (const float*)d_in[8];
    const float* ad2 = (const float*)d_in[9];
    const float* b2  = (const float*)d_in[10];
    const float* W3  = (const float*)d_in[11];
    const float* as3 = (const float*)d_in[12];
    const float* ad3 = (const float*)d_in[13];
    const float* b3  = (const float*)d_in[14];
    const float* Wn  = (const float*)d_in[15];
    const float* bn  = (const float*)d_in[16];
    const float* W0  = (const float*)d_in[17];
    const float* b0  = (const float*)d_in[18];
    const float* Wl  = (const float*)d_in[19];
    const float* bl  = (const float*)d_in[20];
    const float* Wa1 = (const float*)d_in[21];
    const float* ba1 = (const float*)d_in[22];
    const float* v1  = (const float*)d_in[23];
    const float* Wa2 = (const float*)d_in[24];
    const float* ba2 = (const float*)d_in[25];
    const float* v2  = (const float*)d_in[26];
    float* out = (float*)d_out;

    static cudaStream_t s2 = nullptr;
    static cudaEvent_t evF = nullptr, evJ = nullptr;
    if (!s2) {
        cudaStreamCreateWithFlags(&s2, cudaStreamNonBlocking);
        cudaEventCreateWithFlags(&evF, cudaEventDisableTiming);
        cudaEventCreateWithFlags(&evJ, cudaEventDisableTiming);
        cudaFuncSetAttribute(k_gemm_tc, cudaFuncAttributeMaxDynamicSharedMemorySize, GSMEM);
        cudaFuncSetAttribute(k_ag, cudaFuncAttributeMaxDynamicSharedMemorySize, AGS);
    }

    // fork: CSR build + pool init + news projection on s2, GEMM1 on main
    cudaEventRecord(evF, 0);
    cudaStreamWaitEvent(s2, evF, 0);

    k_zero_cnt<<<256, 256, 0, s2>>>();
    k_count<<<512, 256, 0, s2>>>(ei);
    k_scan1<<<NB, 256, 0, s2>>>();
    k_gemm_tc<<<Nn / 128, 256, GSMEM>>>(x, INC, W1, as1, ad1);   // main, profiled slot
    k_scan2<<<1, NB, 0, s2>>>();
    k_scan3<<<NB, 256, 0, s2>>>();
    k_fill<<<512, 256, 0, s2>>>(ei);
    k_pool_init<<<(Gg * Hh + 255) / 256, 256, 0, s2>>>();
    k_news<<<Gg, Hh, 0, s2>>>(x, Wn, bn);

    cudaEventRecord(evJ, s2);
    cudaStreamWaitEvent(0, evJ, 0);

    // fused layer boundaries (main stream)
    k_ag<<<Nn / 128, 256, AGS>>>(b1, 0, W2, as2, ad2);   // agg1 + gemm2: buf0 -> buf1
    k_ag<<<Nn / 128, 256, AGS>>>(b2, 1, W3, as3, ad3);   // agg2 + gemm3: buf1 -> buf0
    k_agg3<<<Nn / 8, 256>>>(b3);                          // agg3 + pool (reads buf0)

    // merged head
    k_head<<<Gg, Hh>>>(W0, b0, Wa1, ba1, Wa2, ba2);
    k_bahfin<<<Gg, Hh>>>(v1, v2, Wl, bl, out);
}

// round 16
// speedup vs baseline: 1.2580x; 1.2580x over previous
#include <cuda_runtime.h>
#include <cuda_bf16.h>
#include <math.h>

#define Nn   131072
#define Ee   1048576
#define ETOT (Ee + Nn)
#define INC  256
#define Hh   128
#define OUTC 64
#define Gg   128
#define NPG  1024
#define NB   256
#define SEG  (Nn / NB)
#define MAXD 64
#define TILEW 4608
#define GSMEM (4 * TILEW * 4)

// ---------------- scratch ----------------
__device__ __align__(16) __nv_bfloat16 g_linh[(size_t)Nn * Hh];
__device__ __align__(16) __nv_bfloat16 g_feath[(size_t)Nn * Hh];
__device__ float g_es[Nn];
__device__ float g_ed[Nn];
__device__ __align__(16) int g_cnt[Nn];
__device__ int   g_off[Nn + 1];
__device__ int   g_cur[Nn];
__device__ int   g_csr[ETOT];
__device__ int   g_bsum[NB];
__device__ __align__(16) float g_pool[Gg * Hh];
__device__ __align__(16) float g_news[Gg * Hh];
__device__ float g_eh1[Gg * OUTC];
__device__ float g_ee1[Gg * OUTC];
__device__ float g_eh2[Gg * OUTC];
__device__ float g_ee2[Gg * OUTC];

__device__ __forceinline__ float atomicMaxF(float* a, float v) {
    if (v >= 0.f) return __int_as_float(atomicMax((int*)a, __float_as_int(v)));
    return __uint_as_float(atomicMin((unsigned int*)a, __float_as_uint(v)));
}

__device__ __forceinline__ void mma_tf32(float* d, const unsigned* a, const unsigned* b) {
    asm volatile(
        "mma.sync.aligned.m16n8k8.row.col.f32.tf32.tf32.f32 "
        "{%0,%1,%2,%3}, {%4,%5,%6,%7}, {%8,%9}, {%0,%1,%2,%3};"
        : "+f"(d[0]), "+f"(d[1]), "+f"(d[2]), "+f"(d[3])
        : "r"(a[0]), "r"(a[1]), "r"(a[2]), "r"(a[3]), "r"(b[0]), "r"(b[1]));
}

__device__ __forceinline__ void cpa16(unsigned dst, const float* src) {
    asm volatile("cp.async.ca.shared.global [%0], [%1], 16;" :: "r"(dst), "l"(src));
}
__device__ __forceinline__ void cpa_commit() { asm volatile("cp.async.commit_group;"); }
__device__ __forceinline__ void cpa_wait()   { asm volatile("cp.async.wait_group 0;"); }

// ---------------- CSR build ----------------
__global__ void k_zero_cnt() {
    int stride = gridDim.x * blockDim.x;
    for (int i = blockIdx.x * blockDim.x + threadIdx.x; i < Nn; i += stride) g_cnt[i] = 1;
}

__global__ void k_count(const int* __restrict__ ei) {
    int stride = gridDim.x * blockDim.x;
    const int4* d4 = (const int4*)(ei + Ee);
    for (int i = blockIdx.x * blockDim.x + threadIdx.x; i < Ee / 4; i += stride) {
        int4 d = d4[i];
        atomicAdd(&g_cnt[d.x], 1);
        atomicAdd(&g_cnt[d.y], 1);
        atomicAdd(&g_cnt[d.z], 1);
        atomicAdd(&g_cnt[d.w], 1);
    }
}

__global__ __launch_bounds__(256) void k_scan1() {
    __shared__ int sm[256];
    int b = blockIdx.x, t = threadIdx.x;
    int2 c = *(const int2*)&g_cnt[b * SEG + t * 2];
    sm[t] = c.x + c.y;
    __syncthreads();
#pragma unroll
    for (int o = 128; o; o >>= 1) {
        if (t < o) sm[t] += sm[t + o];
        __syncthreads();
    }
    if (t == 0) g_bsum[b] = sm[0];
}

__global__ __launch_bounds__(256) void k_scan2() {
    __shared__ int sm[NB];
    int t = threadIdx.x;
    int v = g_bsum[t];
    sm[t] = v;
    __syncthreads();
    for (int o = 1; o < NB; o <<= 1) {
        int u = (t >= o) ? sm[t - o] : 0;
        __syncthreads();
        sm[t] += u;
        __syncthreads();
    }
    g_bsum[t] = sm[t] - v;
}

__global__ __launch_bounds__(256) void k_scan3() {
    __shared__ int sm[256];
    int b = blockIdx.x, t = threadIdx.x;
    int i0 = b * SEG + t * 2;
    int2 c = *(const int2*)&g_cnt[i0];
    int s = c.x + c.y;
    sm[t] = s;
    __syncthreads();
    for (int o = 1; o < 256; o <<= 1) {
        int u = (t >= o) ? sm[t - o] : 0;
        __syncthreads();
        sm[t] += u;
        __syncthreads();
    }
    int run = g_bsum[b] + sm[t] - s;
    g_off[i0] = run;
    g_off[i0 + 1] = run + c.x;
    g_csr[run] = i0;
    g_csr[run + c.x] = i0 + 1;
    g_cur[i0] = run + 1;
    g_cur[i0 + 1] = run + c.x + 1;
    if (b == NB - 1 && t == 255) g_off[Nn] = ETOT;
}

__global__ void k_fill(const int* __restrict__ ei) {
    int stride = gridDim.x * blockDim.x;
    const int4* s4 = (const int4*)ei;
    const int4* d4 = (const int4*)(ei + Ee);
    for (int i = blockIdx.x * blockDim.x + threadIdx.x; i < Ee / 4; i += stride) {
        int4 s = s4[i];
        int4 d = d4[i];
        g_csr[atomicAdd(&g_cur[d.x], 1)] = s.x;
        g_csr[atomicAdd(&g_cur[d.y], 1)] = s.y;
        g_csr[atomicAdd(&g_cur[d.z], 1)] = s.z;
        g_csr[atomicAdd(&g_cur[d.w], 1)] = s.w;
    }
}

// ---------------- tf32 tensor-core GEMM (R11 2-stage) ----------------
// A path: xin != null -> fp32 via cp.async; else bf16 g_feath via reg-staged LDG+cvt+STS.
__global__ __launch_bounds__(256, 2) void k_gemm_tc(const float* __restrict__ xin, int K,
                                                    const float* __restrict__ W,
                                                    const float* __restrict__ av,
                                                    const float* __restrict__ dv) {
    extern __shared__ unsigned smu[];
    unsigned* AsB[2] = { smu, smu + TILEW };
    unsigned* BsB[2] = { smu + 2 * TILEW, smu + 3 * TILEW };

    int tid = threadIdx.x;
    int lane = tid & 31;
    int wid = tid >> 5;
    int warp_m = wid & 3;
    int warp_n = wid >> 2;
    int gID = lane >> 2;
    int tID = lane & 3;
    int rowBase = blockIdx.x * 128;
    int NCH = K >> 5;
    bool f32path = (xin != nullptr);

    auto loadA = [&](int buf, int k0) {   // fp32 cp.async path
#pragma unroll
        for (int l = 0; l < 4; l++) {
            int slot = tid + 256 * l;
            int r = slot >> 3;
            int c4 = (slot & 7) << 2;
            unsigned dst = (unsigned)__cvta_generic_to_shared(&AsB[buf][r * 36 + c4]);
            cpa16(dst, xin + (size_t)(rowBase + r) * K + k0 + c4);
        }
        cpa_commit();
    };
    auto ldgAh = [&](int k0, uint2* areg) {   // bf16 path: LDG into regs
#pragma unroll
        for (int l = 0; l < 4; l++) {
            int slot = tid + 256 * l;
            int r = slot >> 3;
            int c4 = (slot & 7) << 2;
            areg[l] = *(const uint2*)(g_feath + (size_t)(rowBase + r) * Hh + k0 + c4);
        }
    };
    auto stsAh = [&](int buf, const uint2* areg) {   // cvt + STS.128
#pragma unroll
        for (int l = 0; l < 4; l++) {
            int slot = tid + 256 * l;
            int r = slot >> 3;
            int c4 = (slot & 7) << 2;
            float2 f01 = __bfloat1622float2(*(const __nv_bfloat162*)&areg[l].x);
            float2 f23 = __bfloat1622float2(*(const __nv_bfloat162*)&areg[l].y);
            float4 v = make_float4(f01.x, f01.y, f23.x, f23.y);
            *(float4*)&AsB[buf][r * 36 + c4] = v;
        }
    };
    auto ldgW = [&](int k0, float* wreg) {
#pragma unroll
        for (int it = 0; it < 16; it++) {
            int c = wid + it * 8;
            int kl = (c & 7) * 4 + tID;
            int n = (c >> 3) * 8 + gID;
            wreg[it] = W[(size_t)(k0 + kl) * 128 + n];
        }
    };
    auto stsW = [&](int buf, const float* wreg) {
#pragma unroll
        for (int it = 0; it < 16; it++) {
            int c = wid + it * 8;
            int kl = (c & 7) * 4 + tID;
            int n = (c >> 3) * 8 + gID;
            BsB[buf][n * 36 + kl] = __float_as_uint(wreg[it]);
        }
    };

    float acc[2][8][4];
#pragma unroll
    for (int mi = 0; mi < 2; mi++)
#pragma unroll
        for (int ni = 0; ni < 8; ni++)
#pragma unroll
            for (int j = 0; j < 4; j++) acc[mi][ni][j] = 0.f;

    if (f32path) loadA(0, 0);
    else {
        uint2 a0[4];
        ldgAh(0, a0);
        stsAh(0, a0);
    }
    {
        float w0[16];
        ldgW(0, w0);
        stsW(0, w0);
    }

    for (int ch = 0; ch < NCH; ch++) {
        int buf = ch & 1;
        bool more = (ch + 1 < NCH);
        float wreg[16];
        uint2 areg[4];
        if (more) {
            ldgW((ch + 1) << 5, wreg);
            if (!f32path) ldgAh((ch + 1) << 5, areg);
        }
        if (f32path) cpa_wait();
        __syncthreads();
        if (more && f32path) loadA(buf ^ 1, (ch + 1) << 5);

        unsigned* As = AsB[buf];
        unsigned* Bs = BsB[buf];
#pragma unroll
        for (int kc = 0; kc < 4; kc++) {
            int kk = kc * 8;
            unsigned af[2][4];
#pragma unroll
            for (int mi = 0; mi < 2; mi++) {
                int r = warp_m * 32 + mi * 16 + gID;
                af[mi][0] = As[r * 36 + kk + tID];
                af[mi][1] = As[(r + 8) * 36 + kk + tID];
                af[mi][2] = As[r * 36 + kk + tID + 4];
                af[mi][3] = As[(r + 8) * 36 + kk + tID + 4];
            }
#pragma unroll
            for (int ni = 0; ni < 8; ni++) {
                int n = warp_n * 64 + ni * 8 + gID;
                unsigned bf[2];
                bf[0] = Bs[n * 36 + kk + tID];
                bf[1] = Bs[n * 36 + kk + tID + 4];
                mma_tf32(acc[0][ni], af[0], bf);
                mma_tf32(acc[1][ni], af[1], bf);
            }
        }
        if (more) {
            stsW(buf ^ 1, wreg);
            if (!f32path) stsAh(buf ^ 1, areg);
        }
    }

    float pes[2][2] = {{0.f, 0.f}, {0.f, 0.f}};
    float ped[2][2] = {{0.f, 0.f}, {0.f, 0.f}};
#pragma unroll
    for (int mi = 0; mi < 2; mi++) {
        int r0 = rowBase + warp_m * 32 + mi * 16 + gID;
        int r1 = r0 + 8;
#pragma unroll
        for (int ni = 0; ni < 8; ni++) {
            int c0 = warp_n * 64 + ni * 8 + 2 * tID;
            float a0v = __ldg(av + c0), a1v = __ldg(av + c0 + 1);
            float d0v = __ldg(dv + c0), d1v = __ldg(dv + c0 + 1);
            float* d = acc[mi][ni];
            __nv_bfloat162 p0, p1;
            p0.x = __float2bfloat16(d[0]); p0.y = __float2bfloat16(d[1]);
            p1.x = __float2bfloat16(d[2]); p1.y = __float2bfloat16(d[3]);
            *(__nv_bfloat162*)(g_linh + (size_t)r0 * Hh + c0) = p0;
            *(__nv_bfloat162*)(g_linh + (size_t)r1 * Hh + c0) = p1;
            pes[mi][0] += d[0] * a0v + d[1] * a1v;
            pes[mi][1] += d[2] * a0v + d[3] * a1v;
            ped[mi][0] += d[0] * d0v + d[1] * d1v;
            ped[mi][1] += d[2] * d0v + d[3] * d1v;
        }
    }
    __syncthreads();
    float* esp = (float*)smu;
#pragma unroll
    for (int mi = 0; mi < 2; mi++)
#pragma unroll
        for (int h = 0; h < 2; h++) {
            float v1 = pes[mi][h], v2 = ped[mi][h];
            v1 += __shfl_xor_sync(0xffffffffu, v1, 1);
            v1 += __shfl_xor_sync(0xffffffffu, v1, 2);
            v2 += __shfl_xor_sync(0xffffffffu, v2, 1);
            v2 += __shfl_xor_sync(0xffffffffu, v2, 2);
            if (tID == 0) {
                int rl = warp_m * 32 + mi * 16 + h * 8 + gID;
                esp[warp_n * 128 + rl] = v1;
                esp[256 + warp_n * 128 + rl] = v2;
            }
        }
    __syncthreads();
    if (tid < 128) {
        g_es[rowBase + tid] = esp[tid] + esp[128 + tid];
        g_ed[rowBase + tid] = esp[256 + tid] + esp[384 + tid];
    }
}

// ---------------- GAT softmax + aggregation (R11 form; bf16 out; agg3 skips write) ----------------
__device__ __forceinline__ void gat_fma(float4& acc, float ex, const uint2& raw) {
    float2 f01 = __bfloat1622float2(*(const __nv_bfloat162*)&raw.x);
    float2 f23 = __bfloat1622float2(*(const __nv_bfloat162*)&raw.y);
    acc.x += ex * f01.x;
    acc.y += ex * f01.y;
    acc.z += ex * f23.x;
    acc.w += ex * f23.y;
}

__global__ __launch_bounds__(256, 8) void k_agg(const float* __restrict__ bias, int dopool) {
    __shared__ float s_t[8][MAXD];
    __shared__ int   s_s[8][MAXD];
    __shared__ float s_pm[128];
    int wip = (threadIdx.x >> 5) & 7;
    int lane = threadIdx.x & 31;
    int d = blockIdx.x * 8 + wip;
    int beg = g_off[d], end = g_off[d + 1];
    int deg = end - beg;
    float edv = g_ed[d];

    float den = 0.f;
    for (int k = lane; k < deg; k += 32) {
        int s = g_csr[beg + k];
        float t = g_es[s] + edv;
        t = (t >= 0.f) ? t : 0.2f * t;
        float ex = __expf(t);
        den += ex;
        if (k < MAXD) { s_t[wip][k] = ex; s_s[wip][k] = s; }
    }
#pragma unroll
    for (int o = 16; o; o >>= 1) den += __shfl_xor_sync(0xffffffffu, den, o);
    __syncwarp();

    float4 acc = make_float4(0.f, 0.f, 0.f, 0.f);
    float4 acc2 = make_float4(0.f, 0.f, 0.f, 0.f);
    int kc = (deg < MAXD) ? deg : MAXD;
    int k = 0;
    for (; k + 4 <= kc; k += 4) {
        float e0 = s_t[wip][k + 0], e1 = s_t[wip][k + 1];
        float e2 = s_t[wip][k + 2], e3 = s_t[wip][k + 3];
        int r0 = s_s[wip][k + 0], r1 = s_s[wip][k + 1];
        int r2 = s_s[wip][k + 2], r3 = s_s[wip][k + 3];
        uint2 q0 = *((const uint2*)(g_linh + (size_t)r0 * Hh) + lane);
        uint2 q1 = *((const uint2*)(g_linh + (size_t)r1 * Hh) + lane);
        uint2 q2 = *((const uint2*)(g_linh + (size_t)r2 * Hh) + lane);
        uint2 q3 = *((const uint2*)(g_linh + (size_t)r3 * Hh) + lane);
        gat_fma(acc, e0, q0);
        gat_fma(acc2, e1, q1);
        gat_fma(acc, e2, q2);
        gat_fma(acc2, e3, q3);
    }
    for (; k < kc; k++) {
        float ex = s_t[wip][k];
        int   sk = s_s[wip][k];
        uint2 q0 = *((const uint2*)(g_linh + (size_t)sk * Hh) + lane);
        gat_fma(acc, ex, q0);
    }
    for (k = MAXD; k < deg; k++) {
        int sk = g_csr[beg + k];
        float t = g_es[sk] + edv;
        t = (t >= 0.f) ? t : 0.2f * t;
        float ex = __expf(t);
        uint2 q0 = *((const uint2*)(g_linh + (size_t)sk * Hh) + lane);
        gat_fma(acc, ex, q0);
    }
    acc.x += acc2.x;
    acc.y += acc2.y;
    acc.z += acc2.z;
    acc.w += acc2.w;

    float inv = 1.f / (den + 1e-16f);
    float4 bv = *((const float4*)bias + lane);
    float4 r;
    r.x = fmaxf(acc.x * inv + bv.x, 0.f);
    r.y = fmaxf(acc.y * inv + bv.y, 0.f);
    r.z = fmaxf(acc.z * inv + bv.z, 0.f);
    r.w = fmaxf(acc.w * inv + bv.w, 0.f);

    if (!dopool) {
        __nv_bfloat162 h01, h23;
        h01.x = __float2bfloat16(r.x); h01.y = __float2bfloat16(r.y);
        h23.x = __float2bfloat16(r.z); h23.y = __float2bfloat16(r.w);
        uint2 hw;
        hw.x = *(unsigned*)&h01;
        hw.y = *(unsigned*)&h23;
        *((uint2*)(g_feath + (size_t)d * Hh) + lane) = hw;
    } else {   // layer 3: feed pool only
        if (threadIdx.x < 128) s_pm[threadIdx.x] = 0.f;
        __syncthreads();
        atomicMaxF(&s_pm[lane * 4 + 0], r.x);
        atomicMaxF(&s_pm[lane * 4 + 1], r.y);
        atomicMaxF(&s_pm[lane * 4 + 2], r.z);
        atomicMaxF(&s_pm[lane * 4 + 3], r.w);
        __syncthreads();
        if (threadIdx.x < 128) {
            int g = (blockIdx.x * 8) >> 10;
            atomicMaxF(&g_pool[g * Hh + threadIdx.x], s_pm[threadIdx.x]);
        }
    }
}

// ---------------- pool init ----------------
__global__ void k_pool_init() {
    int i = blockIdx.x * blockDim.x + threadIdx.x;
    if (i < Gg * Hh) g_pool[i] = 0.f;
}

// ---------------- news projection ----------------
__global__ void k_news(const float* __restrict__ x,
                       const float* __restrict__ Wn, const float* __restrict__ bn) {
    __shared__ float arow[INC];
    int i = blockIdx.x, j = threadIdx.x;
    for (int k = j; k < INC; k += Hh) arow[k] = x[(long long)i * NPG * INC + k];
    __syncthreads();
    float s = bn[j];
    for (int k = 0; k < INC; k++) s += arow[k] * Wn[k * Hh + j];
    g_news[i * Hh + j] = fmaxf(s, 0.f);
}

// ---------------- merged head ----------------
__global__ void k_head(const float* __restrict__ W0, const float* __restrict__ b0,
                       const float* __restrict__ Wa1, const float* __restrict__ ba1,
                       const float* __restrict__ Wa2, const float* __restrict__ ba2) {
    __shared__ float hg[Hh], nw[Hh], pr[Hh];
    int i = blockIdx.x, j = threadIdx.x;
    pr[j] = g_pool[i * Hh + j];
    nw[j] = g_news[i * Hh + j];
    __syncthreads();
    float s = b0[j];
    for (int k = 0; k < Hh; k++) s += pr[k] * W0[k * Hh + j];
    hg[j] = fmaxf(s, 0.f);
    __syncthreads();
#pragma unroll
    for (int q = 0; q < 2; q++) {
        int o = j + q * 128;
        int y = o >> 6, c = o & 63;
        const float* Arow = (y == 0 || y == 3) ? hg : nw;
        const float* W = (y == 0) ? Wa1 : (y == 1) ? (Wa1 + Hh * OUTC)
                       : (y == 2) ? Wa2 : (Wa2 + Hh * OUTC);
        float acc = (y == 0) ? ba1[c] : (y == 2) ? ba2[c] : 0.f;
        for (int k = 0; k < Hh; k++) acc += Arow[k] * W[k * OUTC + c];
        float* C = (y == 0) ? g_eh1 : (y == 1) ? g_ee1 : (y == 2) ? g_eh2 : g_ee2;
        C[i * OUTC + c] = acc;
    }
}

// ---------------- merged Bahdanau + final ----------------
__global__ void k_bahfin(const float* __restrict__ v1, const float* __restrict__ v2,
                         const float* __restrict__ Wl, const float* __restrict__ bl,
                         float* __restrict__ out) {
    __shared__ float se1[OUTC], se2[OUTC], sv1[OUTC], sv2[OUTC];
    __shared__ float fused[2 * Hh];
    int i = blockIdx.x, j = threadIdx.x;
    if (j < OUTC) { se1[j] = g_eh1[i * OUTC + j]; sv1[j] = v1[j]; }
    else          { int c = j - OUTC; se2[c] = g_eh2[i * OUTC + c]; sv2[c] = v2[c]; }
    __syncthreads();
    float a = 0.f, b = 0.f;
#pragma unroll 8
    for (int k = 0; k < OUTC; k++) a += tanhf(se1[k] + g_ee1[j * OUTC + k]) * sv1[k];
#pragma unroll 8
    for (int k = 0; k < OUTC; k++) b += tanhf(se2[k] + g_ee2[j * OUTC + k]) * sv2[k];
    fused[j] = a;
    fused[Hh + j] = b;
    __syncthreads();
    if (j < OUTC) {
        float s = bl[j];
        for (int k = 0; k < 2 * Hh; k++) s += fused[k] * Wl[k * OUTC + j];
        out[i * OUTC + j] = 1.f / (1.f + __expf(-s));
    }
}

// ---------------- launch ----------------
extern "C" void kernel_launch(void* const* d_in, const int* in_sizes, int n_in,
                              void* d_out, int out_size) {
    const float* x   = (const float*)d_in[0];
    const int*   ei  = (const int*)d_in[1];
    const float* W1  = (const float*)d_in[3];
    const float* as1 = (const float*)d_in[4];
    const float* ad1 = (const float*)d_in[5];
    const float* b1  = (const float*)d_in[6];
    const float* W2  = (const float*)d_in[7];
    const float* as2 = (const float*)d_in[8];
    const float* ad2 = (const float*)d_in[9];
    const float* b2  = (const float*)d_in[10];
    const float* W3  = (const float*)d_in[11];
    const float* as3 = (const float*)d_in[12];
    const float* ad3 = (const float*)d_in[13];
    const float* b3  = (const float*)d_in[14];
    const float* Wn  = (const float*)d_in[15];
    const float* bn  = (const float*)d_in[16];
    const float* W0  = (const float*)d_in[17];
    const float* b0  = (const float*)d_in[18];
    const float* Wl  = (const float*)d_in[19];
    const float* bl  = (const float*)d_in[20];
    const float* Wa1 = (const float*)d_in[21];
    const float* ba1 = (const float*)d_in[22];
    const float* v1  = (const float*)d_in[23];
    const float* Wa2 = (const float*)d_in[24];
    const float* ba2 = (const float*)d_in[25];
    const float* v2  = (const float*)d_in[26];
    float* out = (float*)d_out;

    static cudaStream_t s2 = nullptr;
    static cudaEvent_t evF = nullptr, evJ = nullptr;
    if (!s2) {
        cudaStreamCreateWithFlags(&s2, cudaStreamNonBlocking);
        cudaEventCreateWithFlags(&evF, cudaEventDisableTiming);
        cudaEventCreateWithFlags(&evJ, cudaEventDisableTiming);
        cudaFuncSetAttribute(k_gemm_tc, cudaFuncAttributeMaxDynamicSharedMemorySize, GSMEM);
    }

    // fork: CSR build + pool init + news projection on s2, GEMM1 on main
    cudaEventRecord(evF, 0);
    cudaStreamWaitEvent(s2, evF, 0);

    k_zero_cnt<<<256, 256, 0, s2>>>();
    k_count<<<512, 256, 0, s2>>>(ei);
    k_scan1<<<NB, 256, 0, s2>>>();
    k_gemm_tc<<<Nn / 128, 256, GSMEM>>>(x, INC, W1, as1, ad1);   // main, profiled slot
    k_scan2<<<1, NB, 0, s2>>>();
    k_scan3<<<NB, 256, 0, s2>>>();
    k_fill<<<512, 256, 0, s2>>>(ei);
    k_pool_init<<<(Gg * Hh + 255) / 256, 256, 0, s2>>>();
    k_news<<<Gg, Hh, 0, s2>>>(x, Wn, bn);

    cudaEventRecord(evJ, s2);
    cudaStreamWaitEvent(0, evJ, 0);

    // GAT layers (main stream)
    k_agg<<<Nn / 8, 256>>>(b1, 0);
    k_gemm_tc<<<Nn / 128, 256, GSMEM>>>(nullptr, Hh, W2, as2, ad2);
    k_agg<<<Nn / 8, 256>>>(b2, 0);
    k_gemm_tc<<<Nn / 128, 256, GSMEM>>>(nullptr, Hh, W3, as3, ad3);
    k_agg<<<Nn / 8, 256>>>(b3, 1);   // layer 3: pool only, no feature write

    // merged head
    k_head<<<Gg, Hh>>>(W0, b0, Wa1, ba1, Wa2, ba2);
    k_bahfin<<<Gg, Hh>>>(v1, v2, Wl, bl, out);
}